// round 8
// baseline (speedup 1.0000x reference)
#include <cuda_runtime.h>
#include <cuda_bf16.h>
#include <math.h>
#include <stdint.h>

// ---------------- problem constants ----------------
#define S_LEN   2048
#define HID     3584
#define NHQ     16
#define NKV     8
#define DH      256
#define GROUPS  2
#define WINDOW  1024
#define BANDW   1152
#define SOFTCAP 50.0f
#define SCALING 0.0625f

typedef __nv_bfloat16 bf16;

// ---------------- device scratch ----------------
__device__ float g_Q [(size_t)S_LEN * NHQ * DH];
__device__ float g_K [(size_t)S_LEN * NKV * DH];
__device__ float g_V [(size_t)S_LEN * NKV * DH];
__device__ float g_S [(size_t)NHQ * S_LEN * BANDW];

__device__ bf16 g_hsH[(size_t)S_LEN * HID],      g_hsL[(size_t)S_LEN * HID];
__device__ bf16 g_wqH[(size_t)NHQ * DH * HID],   g_wqL[(size_t)NHQ * DH * HID];
__device__ bf16 g_wkH[(size_t)NKV * DH * HID],   g_wkL[(size_t)NKV * DH * HID];
__device__ bf16 g_wvH[(size_t)NKV * DH * HID],   g_wvL[(size_t)NKV * DH * HID];
__device__ bf16 g_woH[(size_t)HID * NHQ * DH],   g_woL[(size_t)HID * NHQ * DH];
__device__ bf16 g_QH [(size_t)S_LEN * NHQ * DH], g_QL [(size_t)S_LEN * NHQ * DH];
__device__ bf16 g_KH [(size_t)S_LEN * NKV * DH], g_KL [(size_t)S_LEN * NKV * DH];
__device__ bf16 g_VtH[(size_t)NKV * DH * S_LEN], g_VtL[(size_t)NKV * DH * S_LEN];
__device__ bf16 g_PH [(size_t)NHQ * S_LEN * BANDW], g_PL[(size_t)NHQ * S_LEN * BANDW];
__device__ bf16 g_AOH[(size_t)S_LEN * NHQ * DH], g_AOL[(size_t)S_LEN * NHQ * DH];

// ---------------- helpers ----------------
__device__ __forceinline__ uint32_t smem_u32(const void* p) {
    uint32_t a;
    asm("{ .reg .u64 t; cvta.to.shared.u64 t, %1; cvt.u32.u64 %0, t; }" : "=r"(a) : "l"(p));
    return a;
}
__device__ __forceinline__ void cp16(uint32_t saddr, const void* g) {
    asm volatile("cp.async.cg.shared.global [%0], [%1], 16;" :: "r"(saddr), "l"(g) : "memory");
}
#define CP_COMMIT() asm volatile("cp.async.commit_group;" ::: "memory")

#define LDSM4(r0, r1, r2, r3, addr) \
    asm volatile("ldmatrix.sync.aligned.m8n8.x4.shared.b16 {%0,%1,%2,%3}, [%4];" \
        : "=r"(r0), "=r"(r1), "=r"(r2), "=r"(r3) : "r"(addr))

__device__ __forceinline__ void hmma(float* c,
    uint32_t a0, uint32_t a1, uint32_t a2, uint32_t a3,
    uint32_t b0, uint32_t b1)
{
    asm volatile(
        "mma.sync.aligned.m16n8k16.row.col.f32.bf16.bf16.f32 "
        "{%0,%1,%2,%3}, {%4,%5,%6,%7}, {%8,%9}, {%0,%1,%2,%3};"
        : "+f"(c[0]), "+f"(c[1]), "+f"(c[2]), "+f"(c[3])
        : "r"(a0), "r"(a1), "r"(a2), "r"(a3), "r"(b0), "r"(b1));
}

// ================================================================
// 256x256 projection GEMM: C = A*B^T, split-bf16 x3, fp32 accum
// 512 threads (16 warps, 4x4 grid, warp tile 64x64). K % 32 == 0.
// Stage (64 KB): Ah[256][32] Al Bh Bl, each 16 KB, row pitch 64 B,
// swizzle: seg_store = seg ^ ((row>>1)&3).
// ================================================================
#define STAGE256 65536
#define SMEM256  (2 * STAGE256)

__device__ __forceinline__ void stage_cp256(
    const bf16* __restrict__ Ah, const bf16* __restrict__ Al, int lda,
    const bf16* __restrict__ Bh, const bf16* __restrict__ Bl, int ldb,
    int k0, uint32_t smb, int buf, int tid)
{
    uint32_t sb = smb + buf * STAGE256;
#pragma unroll
    for (int i = 0; i < 2; ++i) {
        int si  = tid + i * 512;       // 0..1023 16B chunks per array
        int row = si >> 2;             // 0..255
        int seg = si & 3;
        uint32_t soff = row * 64 + ((seg ^ ((row >> 1) & 3)) << 4);
        size_t goA = (size_t)row * lda + k0 + seg * 8;
        size_t goB = (size_t)row * ldb + k0 + seg * 8;
        cp16(sb +     0 + soff, Ah + goA);
        cp16(sb + 16384 + soff, Al + goA);
        cp16(sb + 32768 + soff, Bh + goB);
        cp16(sb + 49152 + soff, Bl + goB);
    }
}

__global__ void __launch_bounds__(512, 1)
k_gemm256(const bf16* __restrict__ Ah0, const bf16* __restrict__ Al0, int lda,
          const bf16* __restrict__ Bh0, const bf16* __restrict__ Bl0, int ldb,
          float* __restrict__ C0, int ldc, int K)
{
    extern __shared__ char smem[];
    const uint32_t smb = smem_u32(smem);
    const int tid  = threadIdx.x;
    const int lane = tid & 31;
    const int wid  = tid >> 5;
    const int wm   = wid >> 2;        // 0..3
    const int wn   = wid & 3;         // 0..3
    const int la   = lane & 7;
    const int grp  = lane >> 3;       // 0..3

    const size_t m0 = (size_t)blockIdx.y * 256, n0 = (size_t)blockIdx.x * 256;
    const bf16* Ah = Ah0 + m0 * lda;
    const bf16* Al = Al0 + m0 * lda;
    const bf16* Bh = Bh0 + n0 * ldb;
    const bf16* Bl = Bl0 + n0 * ldb;
    float* C = C0 + m0 * ldc + n0;

    float acc[4][8][4];
#pragma unroll
    for (int mi = 0; mi < 4; ++mi)
#pragma unroll
        for (int ni = 0; ni < 8; ++ni)
#pragma unroll
            for (int q = 0; q < 4; ++q) acc[mi][ni][q] = 0.0f;

    uint32_t offA[4], swA[4];
#pragma unroll
    for (int mi = 0; mi < 4; ++mi) {
        int r = wm * 64 + mi * 16 + la + (grp & 1) * 8;
        offA[mi] = r * 64;
        swA[mi]  = (r >> 1) & 3;
    }
    const int segselA = grp >> 1;
    uint32_t offB[4], swB[4];
#pragma unroll
    for (int p = 0; p < 4; ++p) {
        int r = wn * 64 + p * 16 + la + (grp >> 1) * 8;
        offB[p] = r * 64;
        swB[p]  = (r >> 1) & 3;
    }
    const int segselB = grp & 1;

    const int nK = K >> 5;
    stage_cp256(Ah, Al, lda, Bh, Bl, ldb, 0, smb, 0, tid);
    CP_COMMIT();

    for (int ki = 0; ki < nK; ++ki) {
        if (ki + 1 < nK) {
            stage_cp256(Ah, Al, lda, Bh, Bl, ldb, (ki + 1) << 5, smb, (ki + 1) & 1, tid);
            CP_COMMIT();
            asm volatile("cp.async.wait_group 1;" ::: "memory");
        } else {
            asm volatile("cp.async.wait_group 0;" ::: "memory");
        }
        __syncthreads();

        const uint32_t sA  = smb + (ki & 1) * STAGE256;
        const uint32_t sAl = sA + 16384;
        const uint32_t sB  = sA + 32768;
        const uint32_t sBl = sA + 49152;

#pragma unroll
        for (int ks = 0; ks < 2; ++ks) {
            uint32_t ah[4][4], al[4][4];
#pragma unroll
            for (int mi = 0; mi < 4; ++mi) {
                uint32_t aoff = offA[mi] + ((((uint32_t)(ks * 2 + segselA) ^ swA[mi])) << 4);
                LDSM4(ah[mi][0], ah[mi][1], ah[mi][2], ah[mi][3], sA + aoff);
                LDSM4(al[mi][0], al[mi][1], al[mi][2], al[mi][3], sAl + aoff);
            }
#pragma unroll
            for (int p = 0; p < 4; ++p) {
                uint32_t boff = offB[p] + ((((uint32_t)(ks * 2 + segselB) ^ swB[p])) << 4);
                uint32_t bh0, bh1, bh2, bh3, bl0, bl1, bl2, bl3;
                LDSM4(bh0, bh1, bh2, bh3, sB  + boff);
                LDSM4(bl0, bl1, bl2, bl3, sBl + boff);
#pragma unroll
                for (int mi = 0; mi < 4; ++mi) {
                    float* c0 = acc[mi][2 * p];
                    float* c1 = acc[mi][2 * p + 1];
                    hmma(c0, ah[mi][0], ah[mi][1], ah[mi][2], ah[mi][3], bh0, bh1);
                    hmma(c0, ah[mi][0], ah[mi][1], ah[mi][2], ah[mi][3], bl0, bl1);
                    hmma(c0, al[mi][0], al[mi][1], al[mi][2], al[mi][3], bh0, bh1);
                    hmma(c1, ah[mi][0], ah[mi][1], ah[mi][2], ah[mi][3], bh2, bh3);
                    hmma(c1, ah[mi][0], ah[mi][1], ah[mi][2], ah[mi][3], bl2, bl3);
                    hmma(c1, al[mi][0], al[mi][1], al[mi][2], al[mi][3], bh2, bh3);
                }
            }
        }
        __syncthreads();
    }

    const int g  = lane >> 2;
    const int t4 = lane & 3;
#pragma unroll
    for (int mi = 0; mi < 4; ++mi) {
        int R0 = wm * 64 + mi * 16 + g;
        int R1 = R0 + 8;
#pragma unroll
        for (int ni = 0; ni < 8; ++ni) {
            int col = wn * 64 + ni * 8 + t4 * 2;
            float* a = acc[mi][ni];
            *(float2*)(C + (size_t)R0 * ldc + col) = make_float2(a[0], a[1]);
            *(float2*)(C + (size_t)R1 * ldc + col) = make_float2(a[2], a[3]);
        }
    }
}

// ================================================================
// 128x128 attention GEMM (as round 6/7)
// ================================================================
#define STAGE_BYTES 32768
#define NSTAGE      3
#define SMEM_BYTES  (NSTAGE * STAGE_BYTES)

__device__ __forceinline__ void stage_cp(
    const bf16* __restrict__ Ah, const bf16* __restrict__ Al, int lda,
    const bf16* __restrict__ Bh, const bf16* __restrict__ Bl, int ldb,
    int k0, uint32_t smb, int buf, int tid)
{
    uint32_t sb = smb + buf * STAGE_BYTES;
#pragma unroll
    for (int i = 0; i < 4; ++i) {
        int si  = tid + i * 128;
        int row = si >> 2;
        int seg = si & 3;
        uint32_t soff = row * 64 + ((seg ^ ((row >> 1) & 3)) << 4);
        size_t goA = (size_t)row * lda + k0 + seg * 8;
        size_t goB = (size_t)row * ldb + k0 + seg * 8;
        cp16(sb +     0 + soff, Ah + goA);
        cp16(sb +  8192 + soff, Al + goA);
        cp16(sb + 16384 + soff, Bh + goB);
        cp16(sb + 24576 + soff, Bl + goB);
    }
}

template <int EPI>
__device__ void gemm_hmma_tile(
    const bf16* __restrict__ Ah, const bf16* __restrict__ Al, int lda,
    const bf16* __restrict__ Bh, const bf16* __restrict__ Bl, int ldb,
    float* __restrict__ C, bf16* __restrict__ Ch, bf16* __restrict__ Cl,
    int ldc, int K)
{
    extern __shared__ char smem[];
    const uint32_t smb = smem_u32(smem);
    const int tid  = threadIdx.x;
    const int lane = tid & 31;
    const int wid  = tid >> 5;
    const int wm   = wid >> 1;
    const int wn   = wid & 1;
    const int la   = lane & 7;
    const int grp  = lane >> 3;

    float acc[4][8][4];
#pragma unroll
    for (int mi = 0; mi < 4; ++mi)
#pragma unroll
        for (int ni = 0; ni < 8; ++ni)
#pragma unroll
            for (int q = 0; q < 4; ++q) acc[mi][ni][q] = 0.0f;

    uint32_t offA[4], swA[4];
#pragma unroll
    for (int mi = 0; mi < 4; ++mi) {
        int r = wm * 64 + mi * 16 + la + (grp & 1) * 8;
        offA[mi] = r * 64;
        swA[mi]  = (r >> 1) & 3;
    }
    const int segselA = grp >> 1;
    uint32_t offB[4], swB[4];
#pragma unroll
    for (int p = 0; p < 4; ++p) {
        int r = wn * 64 + p * 16 + la + (grp >> 1) * 8;
        offB[p] = r * 64;
        swB[p]  = (r >> 1) & 3;
    }
    const int segselB = grp & 1;

    const int nK = K >> 5;
    stage_cp(Ah, Al, lda, Bh, Bl, ldb, 0, smb, 0, tid);
    CP_COMMIT();
    if (nK > 1) stage_cp(Ah, Al, lda, Bh, Bl, ldb, 32, smb, 1, tid);
    CP_COMMIT();

    int buf = 0;
    for (int ki = 0; ki < nK; ++ki) {
        __syncthreads();
        if (ki + 2 < nK)
            stage_cp(Ah, Al, lda, Bh, Bl, ldb, (ki + 2) << 5, smb, (ki + 2) % NSTAGE, tid);
        CP_COMMIT();
        asm volatile("cp.async.wait_group %0;" :: "n"(2) : "memory");
        __syncthreads();

        const uint32_t sA  = smb + buf * STAGE_BYTES;
        const uint32_t sAl = sA + 8192;
        const uint32_t sB  = sA + 16384;
        const uint32_t sBl = sA + 24576;

#pragma unroll
        for (int ks = 0; ks < 2; ++ks) {
            uint32_t ah[4][4], al[4][4];
#pragma unroll
            for (int mi = 0; mi < 4; ++mi) {
                uint32_t aoff = offA[mi] + ((((uint32_t)(ks * 2 + segselA) ^ swA[mi])) << 4);
                LDSM4(ah[mi][0], ah[mi][1], ah[mi][2], ah[mi][3], sA + aoff);
                LDSM4(al[mi][0], al[mi][1], al[mi][2], al[mi][3], sAl + aoff);
            }
#pragma unroll
            for (int p = 0; p < 4; ++p) {
                uint32_t boff = offB[p] + ((((uint32_t)(ks * 2 + segselB) ^ swB[p])) << 4);
                uint32_t bh0, bh1, bh2, bh3, bl0, bl1, bl2, bl3;
                LDSM4(bh0, bh1, bh2, bh3, sB  + boff);
                LDSM4(bl0, bl1, bl2, bl3, sBl + boff);
#pragma unroll
                for (int mi = 0; mi < 4; ++mi) {
                    float* c0 = acc[mi][2 * p];
                    float* c1 = acc[mi][2 * p + 1];
                    hmma(c0, ah[mi][0], ah[mi][1], ah[mi][2], ah[mi][3], bh0, bh1);
                    hmma(c0, ah[mi][0], ah[mi][1], ah[mi][2], ah[mi][3], bl0, bl1);
                    hmma(c0, al[mi][0], al[mi][1], al[mi][2], al[mi][3], bh0, bh1);
                    hmma(c1, ah[mi][0], ah[mi][1], ah[mi][2], ah[mi][3], bh2, bh3);
                    hmma(c1, ah[mi][0], ah[mi][1], ah[mi][2], ah[mi][3], bl2, bl3);
                    hmma(c1, al[mi][0], al[mi][1], al[mi][2], al[mi][3], bh2, bh3);
                }
            }
        }
        buf = (buf + 1) % NSTAGE;
    }

    const int g  = lane >> 2;
    const int t4 = lane & 3;
#pragma unroll
    for (int mi = 0; mi < 4; ++mi) {
        int R0 = wm * 64 + mi * 16 + g;
        int R1 = R0 + 8;
#pragma unroll
        for (int ni = 0; ni < 8; ++ni) {
            int col = wn * 64 + ni * 8 + t4 * 2;
            float* a = acc[mi][ni];
            if (EPI == 0) {
                *(float2*)(C + (size_t)R0 * ldc + col) = make_float2(a[0], a[1]);
                *(float2*)(C + (size_t)R1 * ldc + col) = make_float2(a[2], a[3]);
            } else {
                __nv_bfloat162 h0, h1, l0, l1;
                h0.x = __float2bfloat16(a[0]); h0.y = __float2bfloat16(a[1]);
                h1.x = __float2bfloat16(a[2]); h1.y = __float2bfloat16(a[3]);
                l0.x = __float2bfloat16(a[0] - __bfloat162float(h0.x));
                l0.y = __float2bfloat16(a[1] - __bfloat162float(h0.y));
                l1.x = __float2bfloat16(a[2] - __bfloat162float(h1.x));
                l1.y = __float2bfloat16(a[3] - __bfloat162float(h1.y));
                *(__nv_bfloat162*)(Ch + (size_t)R0 * ldc + col) = h0;
                *(__nv_bfloat162*)(Ch + (size_t)R1 * ldc + col) = h1;
                *(__nv_bfloat162*)(Cl + (size_t)R0 * ldc + col) = l0;
                *(__nv_bfloat162*)(Cl + (size_t)R1 * ldc + col) = l1;
            }
        }
    }
}

__global__ void __launch_bounds__(128, 2)
k_attn_s()
{
    int h = blockIdx.z, r = blockIdx.y, cx = blockIdx.x;
    int cbase = (r - 8 > 0) ? (r - 8) : 0;
    int ct = cbase + cx;
    if (ct > r) return;
    size_t aoff = (size_t)r * 128 * (NHQ * DH) + (size_t)h * DH;
    size_t boff = (size_t)ct * 128 * (NKV * DH) + (size_t)(h / GROUPS) * DH;
    float* C = g_S + ((size_t)h * S_LEN + (size_t)r * 128) * BANDW + (size_t)cx * 128;
    gemm_hmma_tile<0>(g_QH + aoff, g_QL + aoff, NHQ * DH,
                      g_KH + boff, g_KL + boff, NKV * DH,
                      C, nullptr, nullptr, BANDW, DH);
}

__global__ void __launch_bounds__(128, 2)
k_attn_pv()
{
    int h = blockIdx.z, r = blockIdx.y, nx = blockIdx.x;
    int c0 = ((r - 8 > 0) ? (r - 8) : 0) * 128;
    size_t aoff = ((size_t)h * S_LEN + (size_t)r * 128) * BANDW;
    size_t boff = ((size_t)(h / GROUPS) * DH + (size_t)nx * 128) * S_LEN + (size_t)c0;
    size_t coff = (size_t)r * 128 * (NHQ * DH) + (size_t)h * DH + (size_t)nx * 128;
    gemm_hmma_tile<1>(g_PH + aoff, g_PL + aoff, BANDW,
                      g_VtH + boff, g_VtL + boff, S_LEN,
                      nullptr, g_AOH + coff, g_AOL + coff, NHQ * DH, BANDW);
}

// ---------------- elementwise kernels ----------------
__global__ void __launch_bounds__(256)
k_split(const float* __restrict__ x, bf16* __restrict__ hi, bf16* __restrict__ lo, int n4)
{
    int i = blockIdx.x * 256 + threadIdx.x;
    if (i >= n4) return;
    float4 v = ((const float4*)x)[i];
    bf16 h0 = __float2bfloat16(v.x), h1 = __float2bfloat16(v.y);
    bf16 h2 = __float2bfloat16(v.z), h3 = __float2bfloat16(v.w);
    __nv_bfloat162 H0; H0.x = h0; H0.y = h1;
    __nv_bfloat162 H1; H1.x = h2; H1.y = h3;
    ((__nv_bfloat162*)hi)[i * 2 + 0] = H0;
    ((__nv_bfloat162*)hi)[i * 2 + 1] = H1;
    __nv_bfloat162 L0, L1;
    L0.x = __float2bfloat16(v.x - __bfloat162float(h0));
    L0.y = __float2bfloat16(v.y - __bfloat162float(h1));
    L1.x = __float2bfloat16(v.z - __bfloat162float(h2));
    L1.y = __float2bfloat16(v.w - __bfloat162float(h3));
    ((__nv_bfloat162*)lo)[i * 2 + 0] = L0;
    ((__nv_bfloat162*)lo)[i * 2 + 1] = L1;
}

__global__ void __launch_bounds__(256)
k_rope_split(const float* __restrict__ cosb, const float* __restrict__ sinb)
{
    int idx = blockIdx.x * 256 + threadIdx.x;
    int d = idx & 127;
    int t = idx >> 7;
    int slot = t % (NHQ + NKV);
    int s = t / (NHQ + NKV);

    float c0 = cosb[s * DH + d],       s0 = sinb[s * DH + d];
    float c1 = cosb[s * DH + d + 128], s1 = sinb[s * DH + d + 128];

    if (slot < NHQ) {
        size_t b = (size_t)s * (NHQ * DH) + slot * DH + d;
        float x0 = g_Q[b], x1 = g_Q[b + 128];
        float y0 = x0 * c0 - x1 * s0;
        float y1 = x1 * c1 + x0 * s1;
        bf16 h0 = __float2bfloat16(y0), h1 = __float2bfloat16(y1);
        g_QH[b] = h0;       g_QH[b + 128] = h1;
        g_QL[b] = __float2bfloat16(y0 - __bfloat162float(h0));
        g_QL[b + 128] = __float2bfloat16(y1 - __bfloat162float(h1));
    } else {
        size_t b = (size_t)s * (NKV * DH) + (slot - NHQ) * DH + d;
        float x0 = g_K[b], x1 = g_K[b + 128];
        float y0 = x0 * c0 - x1 * s0;
        float y1 = x1 * c1 + x0 * s1;
        bf16 h0 = __float2bfloat16(y0), h1 = __float2bfloat16(y1);
        g_KH[b] = h0;       g_KH[b + 128] = h1;
        g_KL[b] = __float2bfloat16(y0 - __bfloat162float(h0));
        g_KL[b + 128] = __float2bfloat16(y1 - __bfloat162float(h1));
    }
}

__global__ void __launch_bounds__(256)
k_vtrans()
{
    __shared__ float t[32][33];
    int bs = blockIdx.x * 32, bo = blockIdx.y * 32;
    int tx = threadIdx.x, ty = threadIdx.y;
#pragma unroll
    for (int j = 0; j < 32; j += 8)
        t[ty + j][tx] = g_V[(size_t)(bs + ty + j) * (NKV * DH) + bo + tx];
    __syncthreads();
#pragma unroll
    for (int j = 0; j < 32; j += 8) {
        float v = t[tx][ty + j];
        size_t o = (size_t)(bo + ty + j) * S_LEN + bs + tx;
        bf16 h = __float2bfloat16(v);
        g_VtH[o] = h;
        g_VtL[o] = __float2bfloat16(v - __bfloat162float(h));
    }
}

__global__ void __launch_bounds__(256)
k_softmax()
{
    int row  = blockIdx.x * 8 + (threadIdx.x >> 5);
    int lane = threadIdx.x & 31;
    int h = row >> 11;
    int q = row & 2047;

    size_t base = ((size_t)h * S_LEN + q) * BANDW;
    const float* p = g_S + base;
    int r  = q >> 7;
    int c0 = ((r - 8 > 0) ? (r - 8) : 0) * 128;
    int kmin = (q - (WINDOW - 1) > 0) ? (q - (WINDOW - 1)) : 0;

    float v[36];
    float m = -1e30f;
#pragma unroll
    for (int i = 0; i < 36; ++i) {
        int j = lane + 32 * i;
        int k = c0 + j;
        float tt;
        if (k >= kmin && k <= q) {
            float x = p[j] * (SCALING / SOFTCAP);
            tt = SOFTCAP * tanhf(x);
        } else {
            tt = -1e30f;
        }
        v[i] = tt;
        m = fmaxf(m, tt);
    }
#pragma unroll
    for (int o = 16; o > 0; o >>= 1)
        m = fmaxf(m, __shfl_xor_sync(0xFFFFFFFFu, m, o));

    float l = 0.0f;
#pragma unroll
    for (int i = 0; i < 36; ++i) {
        v[i] = expf(v[i] - m);
        l += v[i];
    }
#pragma unroll
    for (int o = 16; o > 0; o >>= 1)
        l += __shfl_xor_sync(0xFFFFFFFFu, l, o);

    float inv = 1.0f / l;
#pragma unroll
    for (int i = 0; i < 36; ++i) {
        float pv = v[i] * inv;
        bf16 hh = __float2bfloat16(pv);
        g_PH[base + lane + 32 * i] = hh;
        g_PL[base + lane + 32 * i] = __float2bfloat16(pv - __bfloat162float(hh));
    }
}

// ---------------- launch ----------------
extern "C" void kernel_launch(void* const* d_in, const int* in_sizes, int n_in,
                              void* d_out, int out_size)
{
    const float* hs   = (const float*)d_in[0];
    const float* cosb = (const float*)d_in[1];
    const float* sinb = (const float*)d_in[2];
    const float* wq   = (const float*)d_in[3];
    const float* wk   = (const float*)d_in[4];
    const float* wv   = (const float*)d_in[5];
    const float* wo   = (const float*)d_in[6];
    float* out = (float*)d_out;

    void *pQ, *pK, *pV;
    void *phsH, *phsL, *pwqH, *pwqL, *pwkH, *pwkL, *pwvH, *pwvL, *pwoH, *pwoL, *pAOH, *pAOL;
    cudaGetSymbolAddress(&pQ, g_Q);   cudaGetSymbolAddress(&pK, g_K);
    cudaGetSymbolAddress(&pV, g_V);
    cudaGetSymbolAddress(&phsH, g_hsH); cudaGetSymbolAddress(&phsL, g_hsL);
    cudaGetSymbolAddress(&pwqH, g_wqH); cudaGetSymbolAddress(&pwqL, g_wqL);
    cudaGetSymbolAddress(&pwkH, g_wkH); cudaGetSymbolAddress(&pwkL, g_wkL);
    cudaGetSymbolAddress(&pwvH, g_wvH); cudaGetSymbolAddress(&pwvL, g_wvL);
    cudaGetSymbolAddress(&pwoH, g_woH); cudaGetSymbolAddress(&pwoL, g_woL);
    cudaGetSymbolAddress(&pAOH, g_AOH); cudaGetSymbolAddress(&pAOL, g_AOL);

    cudaFuncSetAttribute(k_gemm256, cudaFuncAttributeMaxDynamicSharedMemorySize, SMEM256);
    cudaFuncSetAttribute(k_attn_s,  cudaFuncAttributeMaxDynamicSharedMemorySize, SMEM_BYTES);
    cudaFuncSetAttribute(k_attn_pv, cudaFuncAttributeMaxDynamicSharedMemorySize, SMEM_BYTES);

    // split inputs to bf16 hi/lo
    int n4;
    n4 = S_LEN * HID / 4;      k_split<<<(n4 + 255) / 256, 256>>>(hs, (bf16*)phsH, (bf16*)phsL, n4);
    n4 = NHQ * DH * HID / 4;   k_split<<<(n4 + 255) / 256, 256>>>(wq, (bf16*)pwqH, (bf16*)pwqL, n4);
    n4 = NKV * DH * HID / 4;   k_split<<<(n4 + 255) / 256, 256>>>(wk, (bf16*)pwkH, (bf16*)pwkL, n4);
    n4 = NKV * DH * HID / 4;   k_split<<<(n4 + 255) / 256, 256>>>(wv, (bf16*)pwvH, (bf16*)pwvL, n4);
    n4 = HID * NHQ * DH / 4;   k_split<<<(n4 + 255) / 256, 256>>>(wo, (bf16*)pwoH, (bf16*)pwoL, n4);

    // QKV projections (NT, 256x256 tiles)
    k_gemm256<<<dim3(NHQ * DH / 256, S_LEN / 256), 512, SMEM256>>>(
        (bf16*)phsH, (bf16*)phsL, HID, (bf16*)pwqH, (bf16*)pwqL, HID, (float*)pQ, NHQ * DH, HID);
    k_gemm256<<<dim3(NKV * DH / 256, S_LEN / 256), 512, SMEM256>>>(
        (bf16*)phsH, (bf16*)phsL, HID, (bf16*)pwkH, (bf16*)pwkL, HID, (float*)pK, NKV * DH, HID);
    k_gemm256<<<dim3(NKV * DH / 256, S_LEN / 256), 512, SMEM256>>>(
        (bf16*)phsH, (bf16*)phsL, HID, (bf16*)pwvH, (bf16*)pwvL, HID, (float*)pV, NKV * DH, HID);

    // RoPE + split, V transpose + split
    k_rope_split<<<(S_LEN * (NHQ + NKV) * 128) / 256, 256>>>(cosb, sinb);
    k_vtrans<<<dim3(S_LEN / 32, (NKV * DH) / 32), dim3(32, 8)>>>();

    // banded scores (HMMA, 128x128)
    k_attn_s<<<dim3(9, S_LEN / 128, NHQ), 128, SMEM_BYTES>>>();

    // softcap + mask + softmax -> split-bf16 P
    k_softmax<<<(NHQ * S_LEN) / 8, 256>>>();

    // PV (HMMA, 128x128) — epilogue writes split-bf16 AO directly
    k_attn_pv<<<dim3(2, S_LEN / 128, NHQ), 128, SMEM_BYTES>>>();

    // output projection (256x256 tiles)
    k_gemm256<<<dim3(HID / 256, S_LEN / 256), 512, SMEM256>>>(
        (bf16*)pAOH, (bf16*)pAOL, NHQ * DH, (bf16*)pwoH, (bf16*)pwoL, NHQ * DH, out, HID, NHQ * DH);
}